// round 3
// baseline (speedup 1.0000x reference)
#include <cuda_runtime.h>
#include <cuda_bf16.h>

// ---------------------------------------------------------------------------
// RandomSpatialDeformation: svf upsample -> scaling&squaring (7) -> upsample
// -> affine+flow warp of x. All intermediates in __device__ globals (no alloc).
// ---------------------------------------------------------------------------

#define BATCH 2
#define SV    10          // svf spatial dim
#define CDIM  80          // coarse (half) dim
#define FDIM  160         // fine (full) dim
#define NSTEP 7

#define C2 (CDIM * CDIM)
#define C3 (CDIM * CDIM * CDIM)          // 512000
#define F2 (FDIM * FDIM)
#define F3 (FDIM * FDIM * FDIM)          // 4096000

#define BC3 (BATCH * C3)                 // 1024000
#define BF3 (BATCH * F3)                 // 8192000

// SoA scratch: component c at offset c * (BATCH*vol)
__device__ float g_va[3 * BC3];          // 12.3 MB
__device__ float g_vb[3 * BC3];          // 12.3 MB
__device__ float g_ue[3 * BF3];          // 98.3 MB

__device__ __forceinline__ float flerp(float a, float b, float t) {
    return fmaf(t, b - a, a);
}

// Trilinear sample of an SoA volume with D^3 spatial extent, NC components,
// component stride CSTRIDE, batch base baseb (= b * D^3). Coords clamped.
template <int D, int NC, int CSTRIDE>
__device__ __forceinline__ void trisample(const float* __restrict__ vol, int baseb,
                                          float z, float y, float x, float* out) {
    const float mx = (float)(D - 1);
    z = fminf(fmaxf(z, 0.0f), mx);
    y = fminf(fmaxf(y, 0.0f), mx);
    x = fminf(fmaxf(x, 0.0f), mx);
    float fz = floorf(z), fy = floorf(y), fx = floorf(x);
    int iz = (int)fz, iy = (int)fy, ix = (int)fx;
    float wz = z - fz, wy = y - fy, wx = x - fx;
    int iz1 = min(iz + 1, D - 1);
    int iy1 = min(iy + 1, D - 1);
    int ix1 = min(ix + 1, D - 1);

    int o00 = baseb + iz * (D * D) + iy * D;
    int o01 = baseb + iz * (D * D) + iy1 * D;
    int o10 = baseb + iz1 * (D * D) + iy * D;
    int o11 = baseb + iz1 * (D * D) + iy1 * D;

#pragma unroll
    for (int c = 0; c < NC; c++) {
        const float* p = vol + c * CSTRIDE;
        float a0 = flerp(p[o00 + ix], p[o00 + ix1], wx);
        float a1 = flerp(p[o01 + ix], p[o01 + ix1], wx);
        float a2 = flerp(p[o10 + ix], p[o10 + ix1], wx);
        float a3 = flerp(p[o11 + ix], p[o11 + ix1], wx);
        float b0 = flerp(a0, a1, wy);
        float b1 = flerp(a2, a3, wy);
        out[c] = flerp(b0, b1, wz);
    }
}

// K1: resize svf [B,10,10,10,3] (AoS) -> g_va [3][B,80^3] (SoA), * 2^-7.
// jax.image.resize 'linear': in = (out+0.5)*in/out - 0.5, edge-renorm == clamp.
__global__ void __launch_bounds__(256) k_resize_svf(const float* __restrict__ svf) {
    int idx = blockIdx.x * 256 + threadIdx.x;
    if (idx >= BC3) return;
    int x = idx % CDIM;
    int y = (idx / CDIM) % CDIM;
    int z = (idx / C2) % CDIM;
    int b = idx / C3;

    float cz = (float)z * 0.125f - 0.4375f;
    float cy = (float)y * 0.125f - 0.4375f;
    float cx = (float)x * 0.125f - 0.4375f;
    const float mx = (float)(SV - 1);
    cz = fminf(fmaxf(cz, 0.0f), mx);
    cy = fminf(fmaxf(cy, 0.0f), mx);
    cx = fminf(fmaxf(cx, 0.0f), mx);
    float fz = floorf(cz), fy = floorf(cy), fx = floorf(cx);
    int iz = (int)fz, iy = (int)fy, ix = (int)fx;
    float wz = cz - fz, wy = cy - fy, wx = cx - fx;
    int iz1 = min(iz + 1, SV - 1);
    int iy1 = min(iy + 1, SV - 1);
    int ix1 = min(ix + 1, SV - 1);

    // svf AoS: (((b*SV+iz)*SV+iy)*SV+ix)*3 + c
    int base = b * SV * SV * SV;
    int p000 = (base + iz * SV * SV + iy * SV + ix) * 3;
    int p001 = (base + iz * SV * SV + iy * SV + ix1) * 3;
    int p010 = (base + iz * SV * SV + iy1 * SV + ix) * 3;
    int p011 = (base + iz * SV * SV + iy1 * SV + ix1) * 3;
    int p100 = (base + iz1 * SV * SV + iy * SV + ix) * 3;
    int p101 = (base + iz1 * SV * SV + iy * SV + ix1) * 3;
    int p110 = (base + iz1 * SV * SV + iy1 * SV + ix) * 3;
    int p111 = (base + iz1 * SV * SV + iy1 * SV + ix1) * 3;

    int lin = b * C3 + z * C2 + y * CDIM + x;
#pragma unroll
    for (int c = 0; c < 3; c++) {
        float a0 = flerp(svf[p000 + c], svf[p001 + c], wx);
        float a1 = flerp(svf[p010 + c], svf[p011 + c], wx);
        float a2 = flerp(svf[p100 + c], svf[p101 + c], wx);
        float a3 = flerp(svf[p110 + c], svf[p111 + c], wx);
        float b0 = flerp(a0, a1, wy);
        float b1 = flerp(a2, a3, wy);
        g_va[c * BC3 + lin] = flerp(b0, b1, wz) * (1.0f / 128.0f);
    }
}

// K2: one scaling-and-squaring step: dst = v + trilinear(v, p + v).
// DIR=0: va->vb, DIR=1: vb->va. Compile-time DIR so addresses constant-fold.
template <int DIR>
__global__ void __launch_bounds__(256) k_square() {
    const float* __restrict__ src = DIR ? g_vb : g_va;
    float* __restrict__ dst = DIR ? g_va : g_vb;
    int idx = blockIdx.x * 256 + threadIdx.x;
    if (idx >= BC3) return;
    int x = idx % CDIM;
    int y = (idx / CDIM) % CDIM;
    int z = (idx / C2) % CDIM;
    int b = idx / C3;

    int lin = b * C3 + z * C2 + y * CDIM + x;
    float vz = src[lin];
    float vy = src[lin + BC3];
    float vx = src[lin + 2 * BC3];

    float s[3];
    trisample<CDIM, 3, BC3>(src, b * C3, (float)z + vz, (float)y + vy, (float)x + vx, s);

    dst[lin]           = vz + s[0];
    dst[lin + BC3]     = vy + s[1];
    dst[lin + 2 * BC3] = vx + s[2];
}

// K3: resize flow field 80^3 -> 160^3 into g_ue (SoA). Result lives in g_vb.
__global__ void __launch_bounds__(256) k_upsample() {
    int idx = blockIdx.x * 256 + threadIdx.x;
    if (idx >= BF3) return;
    int x = idx % FDIM;
    int y = (idx / FDIM) % FDIM;
    int z = (idx / F2) % FDIM;
    int b = idx / F3;

    float cz = (float)z * 0.5f - 0.25f;
    float cy = (float)y * 0.5f - 0.25f;
    float cx = (float)x * 0.5f - 0.25f;

    float s[3];
    trisample<CDIM, 3, BC3>(g_vb, b * C3, cz, cy, cx, s);

    int lin = b * F3 + z * F2 + y * FDIM + x;
    g_ue[lin]           = s[0];
    g_ue[lin + BF3]     = s[1];
    g_ue[lin + 2 * BF3] = s[2];
}

// K4: fused affine + flow sample + image sample.
__global__ void __launch_bounds__(256) k_final(const float* __restrict__ xin,
                                               const float* __restrict__ aff,
                                               float* __restrict__ out) {
    int idx = blockIdx.x * 256 + threadIdx.x;
    if (idx >= BF3) return;
    int x = idx % FDIM;
    int y = (idx / FDIM) % FDIM;
    int z = (idx / F2) % FDIM;
    int b = idx / F3;

    const float* A = aff + b * 16;  // row-major 4x4
    float gz = (float)z - 79.5f;
    float gy = (float)y - 79.5f;
    float gx = (float)x - 79.5f;

    float lz = fmaf(A[0], gz, fmaf(A[1], gy, fmaf(A[2], gx, 79.5f + A[3])));
    float ly = fmaf(A[4], gz, fmaf(A[5], gy, fmaf(A[6], gx, 79.5f + A[7])));
    float lx = fmaf(A[8], gz, fmaf(A[9], gy, fmaf(A[10], gx, 79.5f + A[11])));

    float u[3];
    trisample<FDIM, 3, BF3>(g_ue, b * F3, lz, ly, lx, u);

    float s[1];
    trisample<FDIM, 1, BF3>(xin, b * F3, lz + u[0], ly + u[1], lx + u[2], s);

    out[b * F3 + z * F2 + y * FDIM + x] = s[0];
}

extern "C" void kernel_launch(void* const* d_in, const int* in_sizes, int n_in,
                              void* d_out, int out_size) {
    const float* x = nullptr;
    const float* aff = nullptr;
    const float* svf = nullptr;
    for (int i = 0; i < n_in; i++) {
        if (in_sizes[i] == BATCH * 16) {
            aff = (const float*)d_in[i];
        } else if (in_sizes[i] == BATCH * SV * SV * SV * 3) {
            svf = (const float*)d_in[i];
        } else {
            x = (const float*)d_in[i];
        }
    }

    const int gC = (BC3 + 255) / 256;
    const int gF = (BF3 + 255) / 256;

    k_resize_svf<<<gC, 256>>>(svf);
    // 7 steps: 0:va->vb, 1:vb->va, ... ends (step 6, DIR=0) with result in g_vb
    k_square<0><<<gC, 256>>>();
    k_square<1><<<gC, 256>>>();
    k_square<0><<<gC, 256>>>();
    k_square<1><<<gC, 256>>>();
    k_square<0><<<gC, 256>>>();
    k_square<1><<<gC, 256>>>();
    k_square<0><<<gC, 256>>>();
    k_upsample<<<gF, 256>>>();
    k_final<<<gF, 256>>>(x, aff, (float*)d_out);
}

// round 4
// speedup vs baseline: 1.1792x; 1.1792x over previous
#include <cuda_runtime.h>
#include <cuda_bf16.h>

// ---------------------------------------------------------------------------
// RandomSpatialDeformation: svf upsample -> scaling&squaring (7) -> upsample
// -> affine+flow warp of x.
// Flow fields stored as float4 (z,y,x,0) so every trilinear tap is 1x LDG.128.
// ---------------------------------------------------------------------------

#define BATCH 2
#define SV    10
#define CDIM  80
#define FDIM  160

#define C2 (CDIM * CDIM)
#define C3 (CDIM * CDIM * CDIM)          // 512000
#define F2 (FDIM * FDIM)
#define F3 (FDIM * FDIM * FDIM)          // 4096000

#define BC3 (BATCH * C3)                 // 1024000
#define BF3 (BATCH * F3)                 // 8192000

__device__ float4 g_v4a[BC3];            // 16.4 MB
__device__ float4 g_v4b[BC3];            // 16.4 MB
__device__ float4 g_u4[BF3];             // 131 MB

__device__ __forceinline__ float flerp(float a, float b, float t) {
    return fmaf(t, b - a, a);
}
__device__ __forceinline__ float4 flerp4(float4 a, float4 b, float t) {
    return make_float4(fmaf(t, b.x - a.x, a.x), fmaf(t, b.y - a.y, a.y),
                       fmaf(t, b.z - a.z, a.z), fmaf(t, b.w - a.w, a.w));
}
__device__ __forceinline__ float4 fmadd4(float4 acc, float4 v, float w) {
    return make_float4(fmaf(w, v.x, acc.x), fmaf(w, v.y, acc.y),
                       fmaf(w, v.z, acc.z), fmaf(w, v.w, acc.w));
}
__device__ __forceinline__ float4 fscale4(float4 v, float w) {
    return make_float4(v.x * w, v.y * w, v.z * w, v.w * w);
}

// Trilinear sample of a float4 SoA-of-vec volume, D^3 spatial, clamped.
template <int D>
__device__ __forceinline__ float4 trisample4(const float4* __restrict__ vol,
                                             float z, float y, float x) {
    const float mx = (float)(D - 1);
    z = fminf(fmaxf(z, 0.0f), mx);
    y = fminf(fmaxf(y, 0.0f), mx);
    x = fminf(fmaxf(x, 0.0f), mx);
    float fz = floorf(z), fy = floorf(y), fx = floorf(x);
    int iz = (int)fz, iy = (int)fy, ix = (int)fx;
    float wz = z - fz, wy = y - fy, wx = x - fx;
    int iz1 = min(iz + 1, D - 1);
    int iy1 = min(iy + 1, D - 1);
    int ix1 = min(ix + 1, D - 1);

    const float4* p00 = vol + iz * (D * D) + iy * D;
    const float4* p01 = vol + iz * (D * D) + iy1 * D;
    const float4* p10 = vol + iz1 * (D * D) + iy * D;
    const float4* p11 = vol + iz1 * (D * D) + iy1 * D;

    float4 a0 = flerp4(p00[ix], p00[ix1], wx);
    float4 a1 = flerp4(p01[ix], p01[ix1], wx);
    float4 a2 = flerp4(p10[ix], p10[ix1], wx);
    float4 a3 = flerp4(p11[ix], p11[ix1], wx);
    return flerp4(flerp4(a0, a1, wy), flerp4(a2, a3, wy), wz);
}

// Scalar trilinear sample (for the image x), D^3 spatial, clamped.
template <int D>
__device__ __forceinline__ float trisample1(const float* __restrict__ vol,
                                            float z, float y, float x) {
    const float mx = (float)(D - 1);
    z = fminf(fmaxf(z, 0.0f), mx);
    y = fminf(fmaxf(y, 0.0f), mx);
    x = fminf(fmaxf(x, 0.0f), mx);
    float fz = floorf(z), fy = floorf(y), fx = floorf(x);
    int iz = (int)fz, iy = (int)fy, ix = (int)fx;
    float wz = z - fz, wy = y - fy, wx = x - fx;
    int iz1 = min(iz + 1, D - 1);
    int iy1 = min(iy + 1, D - 1);
    int ix1 = min(ix + 1, D - 1);

    const float* p00 = vol + iz * (D * D) + iy * D;
    const float* p01 = vol + iz * (D * D) + iy1 * D;
    const float* p10 = vol + iz1 * (D * D) + iy * D;
    const float* p11 = vol + iz1 * (D * D) + iy1 * D;

    float a0 = flerp(p00[ix], p00[ix1], wx);
    float a1 = flerp(p01[ix], p01[ix1], wx);
    float a2 = flerp(p10[ix], p10[ix1], wx);
    float a3 = flerp(p11[ix], p11[ix1], wx);
    return flerp(flerp(a0, a1, wy), flerp(a2, a3, wy), wz);
}

// K1: resize svf [B,10,10,10,3] (AoS) -> g_v4a [B,80^3] float4, * 2^-7.
__global__ void __launch_bounds__(256) k_resize_svf(const float* __restrict__ svf) {
    int idx = blockIdx.x * 256 + threadIdx.x;
    if (idx >= BC3) return;
    int x = idx % CDIM;
    int y = (idx / CDIM) % CDIM;
    int z = (idx / C2) % CDIM;
    int b = idx / C3;

    float cz = (float)z * 0.125f - 0.4375f;
    float cy = (float)y * 0.125f - 0.4375f;
    float cx = (float)x * 0.125f - 0.4375f;
    const float mx = (float)(SV - 1);
    cz = fminf(fmaxf(cz, 0.0f), mx);
    cy = fminf(fmaxf(cy, 0.0f), mx);
    cx = fminf(fmaxf(cx, 0.0f), mx);
    float fz = floorf(cz), fy = floorf(cy), fx = floorf(cx);
    int iz = (int)fz, iy = (int)fy, ix = (int)fx;
    float wz = cz - fz, wy = cy - fy, wx = cx - fx;
    int iz1 = min(iz + 1, SV - 1);
    int iy1 = min(iy + 1, SV - 1);
    int ix1 = min(ix + 1, SV - 1);

    int base = b * SV * SV * SV;
    int p000 = (base + iz * SV * SV + iy * SV + ix) * 3;
    int p001 = (base + iz * SV * SV + iy * SV + ix1) * 3;
    int p010 = (base + iz * SV * SV + iy1 * SV + ix) * 3;
    int p011 = (base + iz * SV * SV + iy1 * SV + ix1) * 3;
    int p100 = (base + iz1 * SV * SV + iy * SV + ix) * 3;
    int p101 = (base + iz1 * SV * SV + iy * SV + ix1) * 3;
    int p110 = (base + iz1 * SV * SV + iy1 * SV + ix) * 3;
    int p111 = (base + iz1 * SV * SV + iy1 * SV + ix1) * 3;

    float r[3];
#pragma unroll
    for (int c = 0; c < 3; c++) {
        float a0 = flerp(svf[p000 + c], svf[p001 + c], wx);
        float a1 = flerp(svf[p010 + c], svf[p011 + c], wx);
        float a2 = flerp(svf[p100 + c], svf[p101 + c], wx);
        float a3 = flerp(svf[p110 + c], svf[p111 + c], wx);
        float b0 = flerp(a0, a1, wy);
        float b1 = flerp(a2, a3, wy);
        r[c] = flerp(b0, b1, wz) * (1.0f / 128.0f);
    }
    g_v4a[b * C3 + z * C2 + y * CDIM + x] = make_float4(r[0], r[1], r[2], 0.0f);
}

// K2: squaring step dst = v + trilinear(v, p + v). DIR=0: a->b, 1: b->a.
template <int DIR>
__global__ void __launch_bounds__(256) k_square() {
    const float4* __restrict__ src = DIR ? g_v4b : g_v4a;
    float4* __restrict__ dst = DIR ? g_v4a : g_v4b;
    int idx = blockIdx.x * 256 + threadIdx.x;
    if (idx >= BC3) return;
    int x = idx % CDIM;
    int y = (idx / CDIM) % CDIM;
    int z = (idx / C2) % CDIM;
    int b = idx / C3;

    int lin = b * C3 + z * C2 + y * CDIM + x;
    float4 v = src[lin];

    float4 s = trisample4<CDIM>(src + b * C3,
                                (float)z + v.x, (float)y + v.y, (float)x + v.z);

    dst[lin] = make_float4(v.x + s.x, v.y + s.y, v.z + s.z, 0.0f);
}

// K3: 80^3 -> 160^3 upsample, blocked: each thread emits a 2x2x2 fine block
// from a 3x3x3 coarse neighborhood. Fixed weights: even fine coord k' = 2k:
// 0.25*c[k-1] + 0.75*c[k]; odd k' = 2k+1: 0.75*c[k] + 0.25*c[k+1] (clamped).
__global__ void __launch_bounds__(256) k_upsample() {
    int idx = blockIdx.x * 256 + threadIdx.x;
    if (idx >= BC3) return;
    int xb = idx % CDIM;
    int yb = (idx / CDIM) % CDIM;
    int zb = (idx / C2) % CDIM;
    int b = idx / C3;

    int im1 = max(xb - 1, 0), ip1 = min(xb + 1, CDIM - 1);
    int jm1 = max(yb - 1, 0), jp1 = min(yb + 1, CDIM - 1);
    int km1 = max(zb - 1, 0), kp1 = min(zb + 1, CDIM - 1);

    const float4* __restrict__ v = g_v4b + b * C3;
    int zoff[3] = { km1 * C2, zb * C2, kp1 * C2 };
    int yoff[3] = { jm1 * CDIM, yb * CDIM, jp1 * CDIM };

    // acc[dz][dy][dx]
    float4 acc[2][2][2];
#pragma unroll
    for (int a = 0; a < 2; a++)
#pragma unroll
        for (int bb = 0; bb < 2; bb++)
#pragma unroll
            for (int c = 0; c < 2; c++)
                acc[a][bb][c] = make_float4(0.f, 0.f, 0.f, 0.f);

    // z-plane weights: even fine z: {0.25, 0.75, 0}; odd: {0, 0.75, 0.25}
    const float wze[3] = { 0.25f, 0.75f, 0.0f };
    const float wzo[3] = { 0.0f,  0.75f, 0.25f };

#pragma unroll
    for (int p = 0; p < 3; p++) {
        float we = wze[p], wo = wzo[p];
        if (we == 0.0f && wo == 0.0f) continue;
        // load 3x3 plane, fold x then y with fixed weights
        float4 xe[3], xo[3];
#pragma unroll
        for (int r = 0; r < 3; r++) {
            const float4* row = v + zoff[p] + yoff[r];
            float4 cm1 = row[im1];
            float4 c0  = row[xb];
            float4 cp1 = row[ip1];
            xe[r] = fmadd4(fscale4(cm1, 0.25f), c0, 0.75f);
            xo[r] = fmadd4(fscale4(cp1, 0.25f), c0, 0.75f);
        }
        // y fold: even uses rows {0(0.25), 1(0.75)}; odd uses {1(0.75), 2(0.25)}
        float4 pv[2][2];  // [dy][dx]
        pv[0][0] = fmadd4(fscale4(xe[0], 0.25f), xe[1], 0.75f);
        pv[0][1] = fmadd4(fscale4(xo[0], 0.25f), xo[1], 0.75f);
        pv[1][0] = fmadd4(fscale4(xe[2], 0.25f), xe[1], 0.75f);
        pv[1][1] = fmadd4(fscale4(xo[2], 0.25f), xo[1], 0.75f);
        // z accumulate
#pragma unroll
        for (int dy = 0; dy < 2; dy++)
#pragma unroll
            for (int dx = 0; dx < 2; dx++) {
                if (we != 0.0f) acc[0][dy][dx] = fmadd4(acc[0][dy][dx], pv[dy][dx], we);
                if (wo != 0.0f) acc[1][dy][dx] = fmadd4(acc[1][dy][dx], pv[dy][dx], wo);
            }
    }

    float4* __restrict__ u = g_u4 + b * F3;
    int fz = 2 * zb, fy = 2 * yb, fx = 2 * xb;
#pragma unroll
    for (int dz = 0; dz < 2; dz++)
#pragma unroll
        for (int dy = 0; dy < 2; dy++)
#pragma unroll
            for (int dx = 0; dx < 2; dx++)
                u[(fz + dz) * F2 + (fy + dy) * FDIM + (fx + dx)] = acc[dz][dy][dx];
}

// K4: fused affine + flow sample + image sample.
__global__ void __launch_bounds__(256) k_final(const float* __restrict__ xin,
                                               const float* __restrict__ aff,
                                               float* __restrict__ out) {
    int idx = blockIdx.x * 256 + threadIdx.x;
    if (idx >= BF3) return;
    int x = idx % FDIM;
    int y = (idx / FDIM) % FDIM;
    int z = (idx / F2) % FDIM;
    int b = idx / F3;

    const float* A = aff + b * 16;  // row-major 4x4
    float gz = (float)z - 79.5f;
    float gy = (float)y - 79.5f;
    float gx = (float)x - 79.5f;

    float lz = fmaf(A[0], gz, fmaf(A[1], gy, fmaf(A[2], gx, 79.5f + A[3])));
    float ly = fmaf(A[4], gz, fmaf(A[5], gy, fmaf(A[6], gx, 79.5f + A[7])));
    float lx = fmaf(A[8], gz, fmaf(A[9], gy, fmaf(A[10], gx, 79.5f + A[11])));

    float4 u = trisample4<FDIM>(g_u4 + b * F3, lz, ly, lx);
    float s = trisample1<FDIM>(xin + b * F3, lz + u.x, ly + u.y, lx + u.z);

    out[b * F3 + z * F2 + y * FDIM + x] = s;
}

extern "C" void kernel_launch(void* const* d_in, const int* in_sizes, int n_in,
                              void* d_out, int out_size) {
    const float* x = nullptr;
    const float* aff = nullptr;
    const float* svf = nullptr;
    for (int i = 0; i < n_in; i++) {
        if (in_sizes[i] == BATCH * 16) {
            aff = (const float*)d_in[i];
        } else if (in_sizes[i] == BATCH * SV * SV * SV * 3) {
            svf = (const float*)d_in[i];
        } else {
            x = (const float*)d_in[i];
        }
    }

    const int gC = (BC3 + 255) / 256;
    const int gF = (BF3 + 255) / 256;

    k_resize_svf<<<gC, 256>>>(svf);
    // 7 steps: ends (DIR=0 last) with result in g_v4b
    k_square<0><<<gC, 256>>>();
    k_square<1><<<gC, 256>>>();
    k_square<0><<<gC, 256>>>();
    k_square<1><<<gC, 256>>>();
    k_square<0><<<gC, 256>>>();
    k_square<1><<<gC, 256>>>();
    k_square<0><<<gC, 256>>>();
    k_upsample<<<gC, 256>>>();
    k_final<<<gF, 256>>>(x, aff, (float*)d_out);
}